// round 1
// baseline (speedup 1.0000x reference)
#include <cuda_runtime.h>
#include <cstdint>
#include <cstddef>

#define N_FEAT 20000
#define BINS   64
#define DOUT   256
#define BATCH  4096
#define TILE_N 128
#define MASKW  ((N_FEAT + 31) / 32)   // 625

// Scratch (static device globals — no runtime allocation)
__device__ float g_t[(size_t)DOUT * N_FEAT];   // (256, 20000) t = (logits+gumbel)/temp
__device__ float g_rowVal[DOUT];
__device__ int   g_rowArg[DOUT];
__device__ float g_logZ[DOUT];
__device__ int   g_sel[DOUT];

__device__ __forceinline__ float negInf() { return __int_as_float(0xff800000); }

__device__ __forceinline__ void pairMax(float& v, int& i, float ov, int oi) {
    if (ov > v || (ov == v && oi < i)) { v = ov; i = oi; }
}
__device__ __forceinline__ void warpReducePair(float& v, int& i) {
    #pragma unroll
    for (int off = 16; off; off >>= 1) {
        float ov = __shfl_down_sync(0xffffffffu, v, off);
        int   oi = __shfl_down_sync(0xffffffffu, i, off);
        pairMax(v, i, ov, oi);
    }
}

// ---------------------------------------------------------------------------
// Kernel 1: m = u @ tinyW (per-n row), softmax over 256 bins -> al,
//           t[d][n] = (log(10*clip(al)) + gumbel[d][n]) / temp, stored (256,20000)
// Block: 256 threads (thread = output column d), TILE_N=128 feature rows per block.
// ---------------------------------------------------------------------------
__global__ void __launch_bounds__(256, 1)
k_compute_t(const float* __restrict__ u, const float* __restrict__ tinyW,
            const float* __restrict__ uniform)
{
    extern __shared__ float sm[];
    float* u_s   = sm;                         // TILE_N * 64
    float* tile  = sm + TILE_N * BINS;         // 256 * (TILE_N+1), padded vs bank conflicts
    float* s_max = tile + DOUT * (TILE_N + 1); // TILE_N
    float* s_sum = s_max + TILE_N;             // TILE_N

    const int tid  = threadIdx.x;
    const int n0   = blockIdx.x * TILE_N;
    const int nCnt = min(TILE_N, N_FEAT - n0);
    const int TS   = TILE_N + 1;

    // tinyW column tid in registers (coalesced loads)
    float w[BINS];
    #pragma unroll
    for (int k = 0; k < BINS; ++k) w[k] = tinyW[k * DOUT + tid];

    for (int i = tid; i < nCnt * BINS; i += 256) u_s[i] = u[n0 * BINS + i];
    __syncthreads();

    // GEMM: m[n][tid]
    for (int n = 0; n < nCnt; ++n) {
        const float* ur = u_s + n * BINS;
        float acc = 0.f;
        #pragma unroll
        for (int k = 0; k < BINS; ++k) acc = fmaf(ur[k], w[k], acc);
        tile[tid * TS + n] = acc;
    }
    __syncthreads();

    // Per-n softmax stats over the 256 bins
    if (tid < nCnt) {
        float mx = negInf();
        for (int d = 0; d < DOUT; ++d) mx = fmaxf(mx, tile[d * TS + tid]);
        float s = 0.f;
        for (int d = 0; d < DOUT; ++d) s += expf(tile[d * TS + tid] - mx);
        s_max[tid] = mx; s_sum[tid] = s;
    }
    __syncthreads();

    // t values, written transposed (d-major) with coalesced n runs
    for (int idx = tid; idx < DOUT * TILE_N; idx += 256) {
        int d = idx >> 7;
        int n = idx & (TILE_N - 1);
        if (n < nCnt) {
            float m  = tile[d * TS + n];
            float al = expf(m - s_max[n]) / s_sum[n];
            al = fminf(fmaxf(al, 1e-7f), 0.9999999f);
            float ug  = uniform[(size_t)d * N_FEAT + n0 + n];
            float gum = -logf(-logf(ug));
            g_t[(size_t)d * N_FEAT + n0 + n] = (logf(10.0f * al) + gum) / 9.9999f;
        }
    }
}

// ---------------------------------------------------------------------------
// Kernel 2: per-row (d) max/argmax over n, and logZ[d] = max + log(sum exp(t-max))
// ---------------------------------------------------------------------------
__global__ void __launch_bounds__(256)
k_rowstats()
{
    __shared__ float redV[8]; __shared__ int redI[8]; __shared__ float redS[8];
    __shared__ float sMx;
    const int d   = blockIdx.x;
    const int tid = threadIdx.x;
    const float* row = g_t + (size_t)d * N_FEAT;

    float bv = negInf(); int bi = 0x7fffffff;
    for (int n = tid; n < N_FEAT; n += 256) {
        float v = row[n];
        if (v > bv) { bv = v; bi = n; }   // ascending n -> first occurrence
    }
    warpReducePair(bv, bi);
    if ((tid & 31) == 0) { redV[tid >> 5] = bv; redI[tid >> 5] = bi; }
    __syncthreads();
    if (tid < 32) {
        bv = (tid < 8) ? redV[tid] : negInf();
        bi = (tid < 8) ? redI[tid] : 0x7fffffff;
        warpReducePair(bv, bi);
        if (tid == 0) { g_rowVal[d] = bv; g_rowArg[d] = bi; sMx = bv; }
    }
    __syncthreads();
    const float mx = sMx;
    float s = 0.f;
    for (int n = tid; n < N_FEAT; n += 256) s += expf(row[n] - mx);
    #pragma unroll
    for (int off = 16; off; off >>= 1) s += __shfl_down_sync(0xffffffffu, s, off);
    if ((tid & 31) == 0) redS[tid >> 5] = s;
    __syncthreads();
    if (tid == 0) {
        float tot = 0.f;
        #pragma unroll
        for (int wdx = 0; wdx < 8; ++wdx) tot += redS[wdx];
        g_logZ[d] = mx + logf(tot);
    }
}

// ---------------------------------------------------------------------------
// Kernel 3: serial greedy selection (256 iterations), single block.
// Cross-row comparison key: t - logZ (monotone in softmax samples).
// Maintains per-row (max, argcol); rescans a row only if its argcol is stolen.
// ---------------------------------------------------------------------------
__global__ void __launch_bounds__(256)
k_select()
{
    __shared__ float sVal[DOUT];
    __shared__ int   sArg[DOUT];
    __shared__ float sLz[DOUT];
    __shared__ unsigned sMask[MASKW];
    __shared__ int sList[DOUT];
    __shared__ int sCount;
    __shared__ int sYs;
    __shared__ float redV[8]; __shared__ int redI[8];

    const int tid = threadIdx.x;
    sVal[tid] = g_rowVal[tid];
    sArg[tid] = g_rowArg[tid];
    sLz[tid]  = g_logZ[tid];
    for (int i = tid; i < MASKW; i += 256) sMask[i] = 0u;
    __syncthreads();

    for (int iter = 0; iter < DOUT; ++iter) {
        // warp 0: global argmax over rows (tie -> lowest row, matching flat argmax)
        if (tid < 32) {
            float bv = negInf(); int bi = 0x7fffffff;
            #pragma unroll
            for (int j = 0; j < 8; ++j) {
                int dd = tid + j * 32;
                if (sArg[dd] >= 0) {
                    float c = sVal[dd] - sLz[dd];
                    pairMax(bv, bi, c, dd);
                }
            }
            warpReducePair(bv, bi);
            if (tid == 0) {
                int x = bi;
                int y = sArg[x];
                g_sel[x] = y;
                sArg[x]  = -1;                       // row dead
                sMask[y >> 5] |= (1u << (y & 31));   // column masked
                sYs = y;
            }
        }
        __syncthreads();
        if (tid == 0) sCount = 0;
        const int y = sYs;
        __syncthreads();

        // rows whose current best column was just stolen
        if (sArg[tid] == y) {
            int p = atomicAdd(&sCount, 1);
            sList[p] = tid;
        }
        __syncthreads();
        const int cnt = sCount;

        for (int r = 0; r < cnt; ++r) {
            const int rowid = sList[r];
            const float* trow = g_t + (size_t)rowid * N_FEAT;
            float bv = negInf(); int bi = 0x7fffffff;
            for (int n = tid; n < N_FEAT; n += 256) {
                if (!((sMask[n >> 5] >> (n & 31)) & 1u)) {
                    float v = trow[n];
                    if (v > bv) { bv = v; bi = n; }
                }
            }
            warpReducePair(bv, bi);
            if ((tid & 31) == 0) { redV[tid >> 5] = bv; redI[tid >> 5] = bi; }
            __syncthreads();
            if (tid < 32) {
                bv = (tid < 8) ? redV[tid] : negInf();
                bi = (tid < 8) ? redI[tid] : 0x7fffffff;
                warpReducePair(bv, bi);
                if (tid == 0) { sVal[rowid] = bv; sArg[rowid] = bi; }
            }
            __syncthreads();
        }
    }
}

// ---------------------------------------------------------------------------
// Kernel 4: Y[b,d] = X[b, sel[d]]  (dl has one 1 per row -> exact column gather)
// ---------------------------------------------------------------------------
__global__ void __launch_bounds__(256)
k_gather(const float* __restrict__ X, float* __restrict__ Y)
{
    const int tid = threadIdx.x;          // = d (block is exactly one b-row chunk of 256)
    const int idx = blockIdx.x * 256 + tid;
    const int b = idx >> 8;
    const int y = g_sel[tid];             // tid == d, coalesced read, L2-hot
    Y[idx] = X[(size_t)b * N_FEAT + y];
}

extern "C" void kernel_launch(void* const* d_in, const int* in_sizes, int n_in,
                              void* d_out, int out_size)
{
    const float* X       = (const float*)d_in[0];
    const float* u       = (const float*)d_in[1];
    const float* tinyW   = (const float*)d_in[2];
    const float* uniform = (const float*)d_in[3];
    float* Y = (float*)d_out;

    const int smem = (TILE_N * BINS + DOUT * (TILE_N + 1) + 2 * TILE_N) * (int)sizeof(float);
    cudaFuncSetAttribute(k_compute_t, cudaFuncAttributeMaxDynamicSharedMemorySize, smem);

    const int nblocks = (N_FEAT + TILE_N - 1) / TILE_N;   // 157
    k_compute_t<<<nblocks, 256, smem>>>(u, tinyW, uniform);
    k_rowstats<<<DOUT, 256>>>();
    k_select<<<1, 256>>>();
    k_gather<<<(BATCH * DOUT) / 256, 256>>>(X, Y);
}

// round 3
// speedup vs baseline: 1.5468x; 1.5468x over previous
#include <cuda_runtime.h>
#include <cstdint>
#include <cstddef>

#define N_FEAT 20000
#define BINS   64
#define DOUT   256
#define BATCH  4096
#define TILE_N 160
#define NBLK   125                    // 125 * 160 == 20000 exactly, single wave
#define MASKW  ((N_FEAT + 31) / 32)   // 625

#define LOG10A   2.302585093f
#define CLIP_LO -16.11809565f         // log(1e-7)
#define CLIP_HI -1.00000005e-7f       // log(0.9999999)
#define INV_T    (1.0f / 9.9999f)

// Scratch (static device globals — no runtime allocation)
__device__ float g_t[(size_t)DOUT * N_FEAT];   // (256, 20000)
__device__ float g_pVal[NBLK * DOUT];
__device__ int   g_pArg[NBLK * DOUT];
__device__ float g_pSum[NBLK * DOUT];
__device__ int   g_sel[DOUT];

__device__ __forceinline__ float negInf() { return __int_as_float(0xff800000); }

__device__ __forceinline__ void pairMax(float& v, int& i, float ov, int oi) {
    if (ov > v || (ov == v && oi < i)) { v = ov; i = oi; }
}
__device__ __forceinline__ void warpReducePair(float& v, int& i) {
    #pragma unroll
    for (int off = 16; off; off >>= 1) {
        float ov = __shfl_down_sync(0xffffffffu, v, off);
        int   oi = __shfl_down_sync(0xffffffffu, i, off);
        pairMax(v, i, ov, oi);
    }
}
__device__ __forceinline__ unsigned long long pack2(float a, float b) {
    unsigned long long r;
    asm("mov.b64 %0, {%1, %2};" : "=l"(r) : "f"(a), "f"(b));
    return r;
}
__device__ __forceinline__ void unpack2(unsigned long long p, float& a, float& b) {
    asm("mov.b64 {%0, %1}, %2;" : "=f"(a), "=f"(b) : "l"(p));
}

// ---------------------------------------------------------------------------
// Kernel 1: m = u @ tinyW (FFMA2 GEMM), algebraic log-softmax over 256 bins,
// t = (log10 + clamp(log al) + gumbel) / temp, stored (256,20000);
// fused per-block row partials (max, argmax, sum exp t).
// Gumbel uses ACCURATE logf: fast __logf near u~1 has huge relative error
// on the winning elements and flips selections (R2 failure, rel_err 0.09).
// ---------------------------------------------------------------------------
__global__ void __launch_bounds__(256, 1)
k_compute_t(const float* __restrict__ u, const float* __restrict__ tinyW,
            const float* __restrict__ uniform)
{
    extern __shared__ float sm[];
    float* u_s  = sm;                          // 160*64 floats, pair-interleaved
    float* tile = sm + TILE_N * BINS;          // 256 * 161 (padded)
    float* s_c  = tile + DOUT * (TILE_N + 1);  // 160: colmax + log(colsum)

    const int tid = threadIdx.x;
    const int lid = tid & 31;
    const int wid = tid >> 5;
    const int n0  = blockIdx.x * TILE_N;
    const int TS  = TILE_N + 1;

    // tinyW column tid, packed {w,w} for FFMA2
    unsigned long long wp[BINS];
    #pragma unroll
    for (int k = 0; k < BINS; ++k) {
        float wk = tinyW[k * DOUT + tid];
        wp[k] = pack2(wk, wk);
    }

    // load u tile, pair-interleaved: {u[n][k], u[n+1][k]} adjacent
    for (int i = tid; i < TILE_N * BINS; i += 256) {
        int n = i >> 6, k = i & 63;
        u_s[((n >> 1) << 7) + (k << 1) + (n & 1)] = u[n0 * BINS + i];
    }
    __syncthreads();

    // Stage A: GEMM, two n at a time via fma.rn.f32x2
    {
        const unsigned long long* u2 = (const unsigned long long*)u_s;
        for (int p = 0; p < TILE_N / 2; ++p) {
            unsigned long long acc = 0ull;   // {0.f, 0.f}
            const unsigned long long* up = u2 + p * BINS;
            #pragma unroll
            for (int k = 0; k < BINS; ++k) {
                asm("fma.rn.f32x2 %0, %1, %2, %0;" : "+l"(acc) : "l"(up[k]), "l"(wp[k]));
            }
            float a0, a1; unpack2(acc, a0, a1);
            tile[tid * TS + 2 * p]     = a0;
            tile[tid * TS + 2 * p + 1] = a1;
        }
    }
    __syncthreads();

    // Stage B: per-column (n) softmax constant c = max_d + log(sum_d exp)
    if (tid < TILE_N) {
        float mx = negInf();
        for (int d = 0; d < DOUT; ++d) mx = fmaxf(mx, tile[d * TS + tid]);
        float s = 0.f;
        for (int d = 0; d < DOUT; ++d) s += __expf(tile[d * TS + tid] - mx);
        s_c[tid] = mx + __logf(s);
    }
    __syncthreads();

    // Stage C: warp-cooperative per-row t + partial (max, arg, sumexp)
    for (int r = 0; r < 32; ++r) {
        const int d = wid * 32 + r;
        float bv = negInf(); int bi = 0x7fffffff; float s = 0.f;
        #pragma unroll
        for (int j = 0; j < TILE_N / 32; ++j) {
            const int n = j * 32 + lid;
            float m   = tile[d * TS + n];
            float lal = fminf(fmaxf(m - s_c[n], CLIP_LO), CLIP_HI);
            float uu  = uniform[(size_t)d * N_FEAT + n0 + n];
            float gum = -logf(-logf(uu));     // ACCURATE logf — selection-critical
            float t   = (LOG10A + lal + gum) * INV_T;
            tile[d * TS + n] = t;
            s += __expf(t);
            if (t > bv) { bv = t; bi = n0 + n; }
        }
        warpReducePair(bv, bi);
        #pragma unroll
        for (int off = 16; off; off >>= 1) s += __shfl_down_sync(0xffffffffu, s, off);
        if (lid == 0) {
            g_pVal[blockIdx.x * DOUT + d] = bv;
            g_pArg[blockIdx.x * DOUT + d] = bi;
            g_pSum[blockIdx.x * DOUT + d] = s;
        }
    }
    __syncthreads();

    // Stage D: coalesced writeback of t
    for (int base = 0; base < DOUT * TILE_N; base += 256) {
        int idx = base + tid;
        int d = idx / TILE_N;
        int n = idx - d * TILE_N;
        g_t[(size_t)d * N_FEAT + n0 + n] = tile[d * TS + n];
    }
}

// ---------------------------------------------------------------------------
// Kernel 2: finalize row stats + serial greedy selection (256 iters), 1 block.
// Key = t - logZ (monotone in softmax). Warp 0 holds all (key,arg) in regs;
// full block participates only in rescans (expected ~1-3 total).
// ---------------------------------------------------------------------------
__global__ void __launch_bounds__(256)
k_select()
{
    __shared__ float sKey[DOUT];
    __shared__ int   sArg[DOUT];
    __shared__ float sLz[DOUT];
    __shared__ unsigned sMask[MASKW];
    __shared__ int sList[DOUT];
    __shared__ int sCnt;
    __shared__ float redV[8]; __shared__ int redI[8];

    const int tid = threadIdx.x;
    const int lid = tid & 31;
    const int wid = tid >> 5;

    // finalize: reduce 125 partials for row d = tid
    {
        float bv = negInf(); int bi = 0x7fffffff; float s = 0.f;
        for (int b = 0; b < NBLK; ++b) {
            float v = g_pVal[b * DOUT + tid];
            int   a = g_pArg[b * DOUT + tid];
            s += g_pSum[b * DOUT + tid];
            if (v > bv) { bv = v; bi = a; }   // ascending block = ascending n
        }
        float lz = __logf(s);
        sKey[tid] = bv - lz;
        sArg[tid] = bi;
        sLz[tid]  = lz;
    }
    for (int i = tid; i < MASKW; i += 256) sMask[i] = 0u;
    __syncthreads();

    // warp 0 register cache: lane lid owns rows j*32+lid, j=0..7
    float key8[8]; int arg8[8];
    if (wid == 0) {
        #pragma unroll
        for (int j = 0; j < 8; ++j) {
            key8[j] = sKey[j * 32 + lid];
            arg8[j] = sArg[j * 32 + lid];
        }
    }
    __syncthreads();

    for (int iter = 0; iter < DOUT; ++iter) {
        if (wid == 0) {
            float bv = negInf(); int bi = 0x7fffffff;
            #pragma unroll
            for (int j = 0; j < 8; ++j) pairMax(bv, bi, key8[j], j * 32 + lid);
            warpReducePair(bv, bi);
            const int x = __shfl_sync(0xffffffffu, bi, 0);
            int y = -1;
            if (lid == (x & 31)) {
                const int j = x >> 5;
                y = arg8[j];
                key8[j] = negInf();
                arg8[j] = -2;
            }
            y = __shfl_sync(0xffffffffu, y, x & 31);
            if (lid == 0) {
                g_sel[x] = y;
                sMask[y >> 5] |= (1u << (y & 31));
                sCnt = 0;
            }
            __syncwarp();
            // stolen rows: alive rows whose cached argmax column just died
            #pragma unroll
            for (int j = 0; j < 8; ++j) {
                if (arg8[j] == y) {
                    int p = atomicAdd(&sCnt, 1);
                    sList[p] = j * 32 + lid;
                }
            }
        }
        __syncthreads();
        const int cnt = sCnt;
        if (cnt > 0) {
            for (int r = 0; r < cnt; ++r) {
                const int row = sList[r];
                const float* trow = g_t + (size_t)row * N_FEAT;
                float bv = negInf(); int bi = 0x7fffffff;
                for (int n = tid; n < N_FEAT; n += 256) {
                    if (!((sMask[n >> 5] >> (n & 31)) & 1u)) {
                        float v = trow[n];
                        if (v > bv) { bv = v; bi = n; }
                    }
                }
                warpReducePair(bv, bi);
                if (lid == 0) { redV[wid] = bv; redI[wid] = bi; }
                __syncthreads();
                if (tid < 32) {
                    bv = (tid < 8) ? redV[tid] : negInf();
                    bi = (tid < 8) ? redI[tid] : 0x7fffffff;
                    warpReducePair(bv, bi);
                    if (tid == 0) { sKey[row] = bv - sLz[row]; sArg[row] = bi; }
                }
                __syncthreads();
            }
            if (wid == 0) {   // refresh register cache for rescanned rows only
                for (int r = 0; r < cnt; ++r) {
                    const int row = sList[r];
                    if (lid == (row & 31)) {
                        key8[row >> 5] = sKey[row];
                        arg8[row >> 5] = sArg[row];
                    }
                }
            }
            __syncthreads();
        }
    }
}

// ---------------------------------------------------------------------------
// Kernel 3: Y[b,d] = X[b, sel[d]]  (dl has one 1 per row -> exact column gather)
// ---------------------------------------------------------------------------
__global__ void __launch_bounds__(256)
k_gather(const float* __restrict__ X, float* __restrict__ Y)
{
    const int tid = threadIdx.x;
    const int idx = blockIdx.x * 256 + tid;
    const int b = idx >> 8;
    const int y = g_sel[tid];             // tid == d
    Y[idx] = X[(size_t)b * N_FEAT + y];
}

extern "C" void kernel_launch(void* const* d_in, const int* in_sizes, int n_in,
                              void* d_out, int out_size)
{
    const float* X       = (const float*)d_in[0];
    const float* u       = (const float*)d_in[1];
    const float* tinyW   = (const float*)d_in[2];
    const float* uniform = (const float*)d_in[3];
    float* Y = (float*)d_out;

    const int smem = (TILE_N * BINS + DOUT * (TILE_N + 1) + TILE_N) * (int)sizeof(float);
    cudaFuncSetAttribute(k_compute_t, cudaFuncAttributeMaxDynamicSharedMemorySize, smem);

    k_compute_t<<<NBLK, 256, smem>>>(u, tinyW, uniform);
    k_select<<<1, 256>>>();
    k_gather<<<(BATCH * DOUT) / 256, 256>>>(X, Y);
}

// round 4
// speedup vs baseline: 2.3429x; 1.5147x over previous
#include <cuda_runtime.h>
#include <cstdint>
#include <cstddef>

#define N_FEAT 20000
#define BINS   64
#define DOUT   256
#define BATCH  4096
#define TILE_N 160
#define NBLK   125                    // 125 * 160 == 20000 exactly, single wave
#define MASKW  ((N_FEAT + 31) / 32)   // 625

#define LOG10A   2.302585093f
#define CLIP_LO -16.11809565f         // log(1e-7)
#define CLIP_HI -1.00000005e-7f       // log(0.9999999)
#define INV_T    (1.0f / 9.9999f)

// Scratch (static device globals — no runtime allocation)
__device__ float g_t[(size_t)DOUT * N_FEAT];   // (256, 20000)
__device__ float g_pVal[NBLK * DOUT];
__device__ int   g_pArg[NBLK * DOUT];
__device__ float g_pSum[NBLK * DOUT];
__device__ int   g_sel[DOUT];

__device__ __forceinline__ float negInf() { return __int_as_float(0xff800000); }

__device__ __forceinline__ void pairMax(float& v, int& i, float ov, int oi) {
    if (ov > v || (ov == v && oi < i)) { v = ov; i = oi; }
}
__device__ __forceinline__ void warpReducePair(float& v, int& i) {
    #pragma unroll
    for (int off = 16; off; off >>= 1) {
        float ov = __shfl_down_sync(0xffffffffu, v, off);
        int   oi = __shfl_down_sync(0xffffffffu, i, off);
        pairMax(v, i, ov, oi);
    }
}
__device__ __forceinline__ unsigned long long pack2(float a, float b) {
    unsigned long long r;
    asm("mov.b64 %0, {%1, %2};" : "=l"(r) : "f"(a), "f"(b));
    return r;
}
__device__ __forceinline__ void unpack2(unsigned long long p, float& a, float& b) {
    asm("mov.b64 {%0, %1}, %2;" : "=f"(a), "=f"(b) : "l"(p));
}
// monotone float->u32 (order-preserving for all finite floats)
__device__ __forceinline__ unsigned monoKey(float f) {
    unsigned u = __float_as_uint(f);
    return (u & 0x80000000u) ? ~u : (u | 0x80000000u);
}

// ---------------------------------------------------------------------------
// Kernel 1: m = u @ tinyW (FFMA2 GEMM), algebraic log-softmax over 256 bins,
// t = (log10 + clamp(log al) + gumbel) / temp, stored (256,20000);
// fused per-block row partials (max, argmax, sum exp t).
// Gumbel uses ACCURATE logf (fast __logf near u~1 flips selections — R2).
// ---------------------------------------------------------------------------
__global__ void __launch_bounds__(256, 1)
k_compute_t(const float* __restrict__ u, const float* __restrict__ tinyW,
            const float* __restrict__ uniform)
{
    extern __shared__ float sm[];
    float* u_s  = sm;                          // 160*64 floats, pair-interleaved
    float* tile = sm + TILE_N * BINS;          // 256 * 161 (padded)
    float* s_c  = tile + DOUT * (TILE_N + 1);  // 160: colmax + log(colsum)

    const int tid = threadIdx.x;
    const int lid = tid & 31;
    const int wid = tid >> 5;
    const int n0  = blockIdx.x * TILE_N;
    const int TS  = TILE_N + 1;

    unsigned long long wp[BINS];
    #pragma unroll
    for (int k = 0; k < BINS; ++k) {
        float wk = tinyW[k * DOUT + tid];
        wp[k] = pack2(wk, wk);
    }

    for (int i = tid; i < TILE_N * BINS; i += 256) {
        int n = i >> 6, k = i & 63;
        u_s[((n >> 1) << 7) + (k << 1) + (n & 1)] = u[n0 * BINS + i];
    }
    __syncthreads();

    // Stage A: GEMM, two n at a time via fma.rn.f32x2
    {
        const unsigned long long* u2 = (const unsigned long long*)u_s;
        for (int p = 0; p < TILE_N / 2; ++p) {
            unsigned long long acc = 0ull;
            const unsigned long long* up = u2 + p * BINS;
            #pragma unroll
            for (int k = 0; k < BINS; ++k) {
                asm("fma.rn.f32x2 %0, %1, %2, %0;" : "+l"(acc) : "l"(up[k]), "l"(wp[k]));
            }
            float a0, a1; unpack2(acc, a0, a1);
            tile[tid * TS + 2 * p]     = a0;
            tile[tid * TS + 2 * p + 1] = a1;
        }
    }
    __syncthreads();

    // Stage B: per-column (n) softmax constant c = max_d + log(sum_d exp)
    if (tid < TILE_N) {
        float mx = negInf();
        for (int d = 0; d < DOUT; ++d) mx = fmaxf(mx, tile[d * TS + tid]);
        float s = 0.f;
        for (int d = 0; d < DOUT; ++d) s += __expf(tile[d * TS + tid] - mx);
        s_c[tid] = mx + __logf(s);
    }
    __syncthreads();

    // Stage C: warp-cooperative per-row t + partial (max, arg, sumexp)
    for (int r = 0; r < 32; ++r) {
        const int d = wid * 32 + r;
        float bv = negInf(); int bi = 0x7fffffff; float s = 0.f;
        #pragma unroll
        for (int j = 0; j < TILE_N / 32; ++j) {
            const int n = j * 32 + lid;
            float m   = tile[d * TS + n];
            float lal = fminf(fmaxf(m - s_c[n], CLIP_LO), CLIP_HI);
            float uu  = uniform[(size_t)d * N_FEAT + n0 + n];
            float gum = -logf(-logf(uu));     // ACCURATE logf — selection-critical
            float t   = (LOG10A + lal + gum) * INV_T;
            tile[d * TS + n] = t;
            s += __expf(t);
            if (t > bv) { bv = t; bi = n0 + n; }
        }
        warpReducePair(bv, bi);
        #pragma unroll
        for (int off = 16; off; off >>= 1) s += __shfl_down_sync(0xffffffffu, s, off);
        if (lid == 0) {
            g_pVal[blockIdx.x * DOUT + d] = bv;
            g_pArg[blockIdx.x * DOUT + d] = bi;
            g_pSum[blockIdx.x * DOUT + d] = s;
        }
    }
    __syncthreads();

    // Stage D: coalesced writeback of t
    for (int base = 0; base < DOUT * TILE_N; base += 256) {
        int idx = base + tid;
        int d = idx / TILE_N;
        int n = idx - d * TILE_N;
        g_t[(size_t)d * N_FEAT + n0 + n] = tile[d * TS + n];
    }
}

// ---------------------------------------------------------------------------
// Kernel 2: finalize row stats, bitonic-sort rows by key desc, then a
// chunked sweep: 32 greedy picks commit at once when conflict-free
// (match_any duplicate check + mask check). Conflicts (expected ~2 total)
// trigger a full-block rescan + tiny pending set merged in key order.
// Produces the EXACT greedy sequence (incl. flat-argmax tie-breaks).
// ---------------------------------------------------------------------------
__global__ void __launch_bounds__(256)
k_select()
{
    __shared__ unsigned long long sC[DOUT];    // sorted composites (ascending)
    __shared__ int   sArg[DOUT];               // cached argmax col, by row
    __shared__ float sLz[DOUT];
    __shared__ unsigned sMask[MASKW];
    __shared__ unsigned long long pC[16];      // pending composites
    __shared__ int sCmd, sRrow, sI, sP;
    __shared__ float redV[8]; __shared__ int redI[8];

    const int tid = threadIdx.x;
    const int lid = tid & 31;
    const int wid = tid >> 5;

    // ---- finalize: reduce 125 partials for row d = tid ----
    {
        float bv = negInf(); int bi = 0x7fffffff; float s = 0.f;
        #pragma unroll 5
        for (int b = 0; b < NBLK; ++b) {
            float v = g_pVal[b * DOUT + tid];
            int   a = g_pArg[b * DOUT + tid];
            s += g_pSum[b * DOUT + tid];
            if (v > bv) { bv = v; bi = a; }   // ascending block = ascending n
        }
        float lz  = __logf(s);
        float key = bv - lz;
        sArg[tid] = bi;
        sLz[tid]  = lz;
        sC[tid] = ((unsigned long long)monoKey(key) << 32) | (unsigned)(255 - tid);
    }
    for (int i = tid; i < MASKW; i += 256) sMask[i] = 0u;
    if (tid == 0) { sI = 0; sP = 0; sCmd = 0; }
    __syncthreads();

    // ---- bitonic sort ascending (rank r = index 255-r) ----
    for (int k = 2; k <= 256; k <<= 1) {
        for (int j = k >> 1; j > 0; j >>= 1) {
            int ixj = tid ^ j;
            if (ixj > tid) {
                unsigned long long a = sC[tid], b = sC[ixj];
                bool sw = ((tid & k) == 0) ? (a > b) : (a < b);
                if (sw) { sC[tid] = b; sC[ixj] = a; }
            }
            __syncthreads();
        }
    }

    // ---- sweep ----
    while (true) {
        if (wid == 0) {
            int i = sI, P = sP;
            int cmd = 0, rrow = -1;
            while (true) {
                if (i >= 256 && P == 0) { cmd = 2; break; }
                if (P == 0) {
                    // fast path: try to commit up to 32 picks at once
                    int r = i + lid;
                    bool valid = r < 256;
                    unsigned long long C = valid ? sC[255 - r] : 0ull;
                    int row = 255 - (int)(C & 0xffffffffu);
                    int a   = valid ? sArg[row] : -1;
                    bool bad = false;
                    unsigned validmask = __ballot_sync(0xffffffffu, valid);
                    unsigned peers = __match_any_sync(0xffffffffu, a) & validmask;
                    if (valid) {
                        bool masked = (sMask[a >> 5] >> (a & 31)) & 1u;
                        bool first  = (peers & ((1u << lid) - 1u)) == 0;
                        bad = masked || !first;
                    }
                    unsigned badmask = __ballot_sync(0xffffffffu, valid && bad);
                    int c = badmask ? ((int)__ffs(badmask) - 1) : 32;
                    int ncommit = min(c, 256 - i);
                    if (lid < ncommit) {
                        atomicOr(&sMask[a >> 5], 1u << (a & 31));
                        g_sel[row] = a;
                    }
                    __syncwarp();
                    i += ncommit;
                    if (c < 32 && i < 256) {
                        // rank i conflicts -> rescan its row
                        unsigned long long Cc = sC[255 - i];
                        rrow = 255 - (int)(Cc & 0xffffffffu);
                        i += 1;
                        cmd = 1; break;
                    }
                } else {
                    // serial merge: sorted head vs best pending (lane 0)
                    int action = 0;
                    if (lid == 0) {
                        bool haveS = i < 256;
                        unsigned long long Cs = haveS ? sC[255 - i] : 0ull;
                        int bj = 0; unsigned long long Cb = pC[0];
                        for (int j = 1; j < P; ++j)
                            if (pC[j] > Cb) { Cb = pC[j]; bj = j; }
                        bool pickP = !haveS || (Cb > Cs);
                        unsigned long long C = pickP ? Cb : Cs;
                        int row = 255 - (int)(C & 0xffffffffu);
                        int a = sArg[row];
                        bool masked = (sMask[a >> 5] >> (a & 31)) & 1u;
                        if (pickP) { pC[bj] = pC[P - 1]; P--; }
                        else i++;
                        if (masked) { sRrow = row; action = 1; }
                        else { sMask[a >> 5] |= 1u << (a & 31); g_sel[row] = a; }
                    }
                    action = __shfl_sync(0xffffffffu, action, 0);
                    i = __shfl_sync(0xffffffffu, i, 0);
                    P = __shfl_sync(0xffffffffu, P, 0);
                    if (action) { rrow = -2; cmd = 1; break; }  // sRrow already set
                }
            }
            if (lid == 0) {
                sCmd = cmd; sI = i; sP = P;
                if (rrow >= 0) sRrow = rrow;
            }
        }
        __syncthreads();
        if (sCmd == 2) break;

        // ---- full-block rescan of sRrow over unmasked columns ----
        {
            const int row = sRrow;
            const float* trow = g_t + (size_t)row * N_FEAT;
            float bv = negInf(); int bi = 0x7fffffff;
            for (int n = tid; n < N_FEAT; n += 256) {
                if (!((sMask[n >> 5] >> (n & 31)) & 1u)) {
                    float v = trow[n];
                    if (v > bv) { bv = v; bi = n; }
                }
            }
            warpReducePair(bv, bi);
            if (lid == 0) { redV[wid] = bv; redI[wid] = bi; }
            __syncthreads();
            if (tid < 32) {
                bv = (tid < 8) ? redV[tid] : negInf();
                bi = (tid < 8) ? redI[tid] : 0x7fffffff;
                warpReducePair(bv, bi);
                if (tid == 0) {
                    sArg[row] = bi;
                    float nk = bv - sLz[row];
                    pC[sP] = ((unsigned long long)monoKey(nk) << 32)
                           | (unsigned)(255 - row);
                    sP = sP + 1;
                    sCmd = 0;
                }
            }
        }
        __syncthreads();
    }
}

// ---------------------------------------------------------------------------
// Kernel 3: Y[b,d] = X[b, sel[d]]  (dl has one 1 per row -> exact column gather)
// ---------------------------------------------------------------------------
__global__ void __launch_bounds__(256)
k_gather(const float* __restrict__ X, float* __restrict__ Y)
{
    const int tid = threadIdx.x;
    const int idx = blockIdx.x * 256 + tid;
    const int b = idx >> 8;
    const int y = g_sel[tid];             // tid == d
    Y[idx] = X[(size_t)b * N_FEAT + y];
}

extern "C" void kernel_launch(void* const* d_in, const int* in_sizes, int n_in,
                              void* d_out, int out_size)
{
    const float* X       = (const float*)d_in[0];
    const float* u       = (const float*)d_in[1];
    const float* tinyW   = (const float*)d_in[2];
    const float* uniform = (const float*)d_in[3];
    float* Y = (float*)d_out;

    const int smem = (TILE_N * BINS + DOUT * (TILE_N + 1) + TILE_N) * (int)sizeof(float);
    cudaFuncSetAttribute(k_compute_t, cudaFuncAttributeMaxDynamicSharedMemorySize, smem);

    k_compute_t<<<NBLK, 256, smem>>>(u, tinyW, uniform);
    k_select<<<1, 256>>>();
    k_gather<<<(BATCH * DOUT) / 256, 256>>>(X, Y);
}

// round 5
// speedup vs baseline: 3.3430x; 1.4268x over previous
#include <cuda_runtime.h>
#include <cstdint>
#include <cstddef>

#define N_FEAT 20000
#define BINS   64
#define DOUT   256
#define BATCH  4096
#define TILE_N 160
#define NBLK   125                    // 125 * 160 == 20000 exactly, single wave
#define MASKW  ((N_FEAT + 31) / 32)   // 625

#define LOG10A   2.302585093f
#define CLIP_LO -16.11809565f         // log(1e-7)
#define CLIP_HI -1.00000005e-7f       // log(0.9999999)
#define INV_T    (1.0f / 9.9999f)

typedef unsigned long long u64;

// Scratch (static device globals — no runtime allocation)
__device__ float g_t[(size_t)DOUT * N_FEAT];   // (256, 20000)
__device__ float g_pSum[DOUT * NBLK];          // [d][b] partial sum exp(t)
__device__ u64   g_top4[DOUT * 4];             // per-row top-4 composites
__device__ float g_logZ[DOUT];
__device__ int   g_sel[DOUT];

__device__ __forceinline__ float negInf() { return __int_as_float(0xff800000); }

__device__ __forceinline__ void pairMax(float& v, int& i, float ov, int oi) {
    if (ov > v || (ov == v && oi < i)) { v = ov; i = oi; }
}
__device__ __forceinline__ void warpReducePair(float& v, int& i) {
    #pragma unroll
    for (int off = 16; off; off >>= 1) {
        float ov = __shfl_down_sync(0xffffffffu, v, off);
        int   oi = __shfl_down_sync(0xffffffffu, i, off);
        pairMax(v, i, ov, oi);
    }
}
__device__ __forceinline__ u64 pack2(float a, float b) {
    u64 r;
    asm("mov.b64 %0, {%1, %2};" : "=l"(r) : "f"(a), "f"(b));
    return r;
}
__device__ __forceinline__ void unpack2(u64 p, float& a, float& b) {
    asm("mov.b64 {%0, %1}, %2;" : "=f"(a), "=f"(b) : "l"(p));
}
// monotone float->u32 (order-preserving)
__device__ __forceinline__ unsigned monoKey(float f) {
    unsigned u = __float_as_uint(f);
    return (u & 0x80000000u) ? ~u : (u | 0x80000000u);
}
__device__ __forceinline__ float unMono(unsigned m) {
    unsigned u = (m & 0x80000000u) ? (m ^ 0x80000000u) : ~m;
    return __uint_as_float(u);
}
// accurate -log(u): series for u near 1 (winners live there), __logf otherwise
__device__ __forceinline__ float neglog_acc(float u) {
    float w  = 1.0f - u;
    float xs = w * (1.0f + w * (0.5f + w * (0.333333333f + w * 0.25f)));
    float xb = -__logf(u);
    return (w < 0.09f) ? xs : xb;
}

// ---------------------------------------------------------------------------
// Kernel 1: m = u @ tinyW (K-SIMD FFMA2, 4 independent acc chains),
// warp-parallel column log-softmax constant, t written straight to g_t,
// per-block row partial sum exp(t) -> g_pSum[d][b].
// ---------------------------------------------------------------------------
__global__ void __launch_bounds__(256, 1)
k_compute_t(const float* __restrict__ u, const float* __restrict__ tinyW,
            const float* __restrict__ uniform)
{
    extern __shared__ float sm[];
    float* u_s  = sm;                          // 160*64, row-major [n][k]
    float* tile = sm + TILE_N * BINS;          // 256 * 161 (padded): m values
    float* s_c  = tile + DOUT * (TILE_N + 1);  // 160: colmax + log(colsum)

    const int tid = threadIdx.x;
    const int lid = tid & 31;
    const int wid = tid >> 5;
    const int n0  = blockIdx.x * TILE_N;
    const int TS  = TILE_N + 1;

    // weights for column d=tid, packed K-pairs {w[2k],w[2k+1]} -> 32 u64 regs
    u64 wp2[BINS / 2];
    #pragma unroll
    for (int k2 = 0; k2 < BINS / 2; ++k2)
        wp2[k2] = pack2(tinyW[(2 * k2) * DOUT + tid], tinyW[(2 * k2 + 1) * DOUT + tid]);

    for (int i = tid; i < TILE_N * BINS; i += 256) u_s[i] = u[n0 * BINS + i];
    __syncthreads();

    // Stage A: GEMM, 4 n per step (independent FFMA2 chains), K-SIMD
    {
        const ulonglong2* uv = (const ulonglong2*)u_s;   // 16B = 4 floats = 2 k-pairs
        for (int q = 0; q < TILE_N; q += 4) {
            u64 a0 = 0ull, a1 = 0ull, a2 = 0ull, a3 = 0ull;
            #pragma unroll
            for (int k4 = 0; k4 < BINS / 4; ++k4) {
                ulonglong2 v0 = uv[(q + 0) * (BINS / 4) + k4];
                ulonglong2 v1 = uv[(q + 1) * (BINS / 4) + k4];
                ulonglong2 v2 = uv[(q + 2) * (BINS / 4) + k4];
                ulonglong2 v3 = uv[(q + 3) * (BINS / 4) + k4];
                asm("fma.rn.f32x2 %0, %1, %2, %0;" : "+l"(a0) : "l"(v0.x), "l"(wp2[2 * k4]));
                asm("fma.rn.f32x2 %0, %1, %2, %0;" : "+l"(a1) : "l"(v1.x), "l"(wp2[2 * k4]));
                asm("fma.rn.f32x2 %0, %1, %2, %0;" : "+l"(a2) : "l"(v2.x), "l"(wp2[2 * k4]));
                asm("fma.rn.f32x2 %0, %1, %2, %0;" : "+l"(a3) : "l"(v3.x), "l"(wp2[2 * k4]));
                asm("fma.rn.f32x2 %0, %1, %2, %0;" : "+l"(a0) : "l"(v0.y), "l"(wp2[2 * k4 + 1]));
                asm("fma.rn.f32x2 %0, %1, %2, %0;" : "+l"(a1) : "l"(v1.y), "l"(wp2[2 * k4 + 1]));
                asm("fma.rn.f32x2 %0, %1, %2, %0;" : "+l"(a2) : "l"(v2.y), "l"(wp2[2 * k4 + 1]));
                asm("fma.rn.f32x2 %0, %1, %2, %0;" : "+l"(a3) : "l"(v3.y), "l"(wp2[2 * k4 + 1]));
            }
            float lo, hi;
            unpack2(a0, lo, hi); tile[tid * TS + q + 0] = lo + hi;
            unpack2(a1, lo, hi); tile[tid * TS + q + 1] = lo + hi;
            unpack2(a2, lo, hi); tile[tid * TS + q + 2] = lo + hi;
            unpack2(a3, lo, hi); tile[tid * TS + q + 3] = lo + hi;
        }
    }
    __syncthreads();

    // Stage B: warp-parallel column stats; warp wid owns n = wid*20 .. +19
    for (int c = 0; c < TILE_N / 8; ++c) {
        const int n = wid * (TILE_N / 8) + c;
        float m[8];
        #pragma unroll
        for (int j = 0; j < 8; ++j) m[j] = tile[(lid + 32 * j) * TS + n];
        float mx = m[0];
        #pragma unroll
        for (int j = 1; j < 8; ++j) mx = fmaxf(mx, m[j]);
        #pragma unroll
        for (int off = 16; off; off >>= 1)
            mx = fmaxf(mx, __shfl_xor_sync(0xffffffffu, mx, off));
        float s = 0.f;
        #pragma unroll
        for (int j = 0; j < 8; ++j) s += __expf(m[j] - mx);
        #pragma unroll
        for (int off = 16; off; off >>= 1) s += __shfl_xor_sync(0xffffffffu, s, off);
        if (lid == 0) s_c[n] = mx + __logf(s);
    }
    __syncthreads();

    // Stage C: per-row t, written straight to g_t; partial sum exp(t)
    for (int r = 0; r < 32; ++r) {
        const int d = wid * 32 + r;
        float s = 0.f;
        #pragma unroll
        for (int j = 0; j < TILE_N / 32; ++j) {
            const int n = j * 32 + lid;
            float m   = tile[d * TS + n];
            float lal = fminf(fmaxf(m - s_c[n], CLIP_LO), CLIP_HI);
            float uu  = uniform[(size_t)d * N_FEAT + n0 + n];
            float x   = neglog_acc(uu);        // -log(u), winner-exact
            float gum = -__logf(x);            // abs-accurate everywhere
            float t   = (LOG10A + lal + gum) * INV_T;
            g_t[(size_t)d * N_FEAT + n0 + n] = t;
            s += __expf(t);
        }
        #pragma unroll
        for (int off = 16; off; off >>= 1) s += __shfl_down_sync(0xffffffffu, s, off);
        if (lid == 0) g_pSum[d * NBLK + blockIdx.x] = s;
    }
}

// ---------------------------------------------------------------------------
// Kernel 2: per-row logZ + top-4 candidates (one block per row).
// Composite = monoKey(t)<<32 | (0xffffffff - n)  (larger = better, ties -> low n)
// ---------------------------------------------------------------------------
__global__ void __launch_bounds__(256)
k_top4()
{
    const int d   = blockIdx.x;
    const int tid = threadIdx.x;
    const int lid = tid & 31;
    const int wid = tid >> 5;
    __shared__ float sS[8];
    __shared__ u64 sW[8];
    __shared__ u64 sWin;

    // logZ
    float s = (tid < NBLK) ? g_pSum[d * NBLK + tid] : 0.f;
    #pragma unroll
    for (int off = 16; off; off >>= 1) s += __shfl_down_sync(0xffffffffu, s, off);
    if (lid == 0) sS[wid] = s;
    __syncthreads();
    if (tid == 0) {
        float tot = 0.f;
        #pragma unroll
        for (int j = 0; j < 8; ++j) tot += sS[j];
        g_logZ[d] = __logf(tot);
    }

    // per-thread sorted top-4
    const float* row = g_t + (size_t)d * N_FEAT;
    u64 c0 = 0, c1 = 0, c2 = 0, c3 = 0;
    for (int n = tid; n < N_FEAT; n += 256) {
        u64 cc = ((u64)monoKey(row[n]) << 32) | (0xffffffffu - (unsigned)n);
        if (cc > c3) {
            if (cc > c2) {
                c3 = c2;
                if (cc > c1) { c2 = c1; if (cc > c0) { c1 = c0; c0 = cc; } else c1 = cc; }
                else c2 = cc;
            } else c3 = cc;
        }
    }
    u64 lst[4] = {c0, c1, c2, c3};
    int pr = 0;

    // 4 rounds of block-argmax over thread heads
    for (int r = 0; r < 4; ++r) {
        u64 h = (pr < 4) ? lst[pr] : 0ull;
        u64 m = h;
        #pragma unroll
        for (int off = 16; off; off >>= 1) {
            u64 o = __shfl_xor_sync(0xffffffffu, m, off);
            if (o > m) m = o;
        }
        if (lid == 0) sW[wid] = m;
        __syncthreads();
        if (tid == 0) {
            u64 w = 0;
            #pragma unroll
            for (int j = 0; j < 8; ++j) if (sW[j] > w) w = sW[j];
            sWin = w;
            g_top4[d * 4 + r] = w;
        }
        __syncthreads();
        if (pr < 4 && h == sWin) pr++;
        __syncthreads();
    }
}

// ---------------------------------------------------------------------------
// Kernel 3: greedy selection via sorted sweep with candidate fallback.
// Block-wide g_t rescan only if a row's 4 candidates are all stolen (~never).
// Produces the EXACT greedy sequence (incl. flat-argmax tie-breaks).
// ---------------------------------------------------------------------------
__global__ void __launch_bounds__(256)
k_select()
{
    __shared__ u64  sC[DOUT];        // sorted composites (ascending)
    __shared__ u64  cand[DOUT][4];
    __shared__ int  sArg[DOUT];      // current proposed column per row
    __shared__ int  sPtr[DOUT];      // next unused candidate
    __shared__ float sLz[DOUT];
    __shared__ unsigned sMask[MASKW];
    __shared__ u64  pC[16];          // pending composites
    __shared__ int  sCmd, sRrow, sI, sP;
    __shared__ float redV[8]; __shared__ int redI[8];

    const int tid = threadIdx.x;
    const int lid = tid & 31;
    const int wid = tid >> 5;

    // init per-row state
    {
        u64 cd0 = g_top4[tid * 4 + 0];
        cand[tid][0] = cd0;
        cand[tid][1] = g_top4[tid * 4 + 1];
        cand[tid][2] = g_top4[tid * 4 + 2];
        cand[tid][3] = g_top4[tid * 4 + 3];
        float lz = g_logZ[tid];
        sLz[tid]  = lz;
        sArg[tid] = (int)(0xffffffffu - (unsigned)(cd0 & 0xffffffffu));
        sPtr[tid] = 1;
        float key = unMono((unsigned)(cd0 >> 32)) - lz;
        sC[tid] = ((u64)monoKey(key) << 32) | (unsigned)(255 - tid);
    }
    for (int i = tid; i < MASKW; i += 256) sMask[i] = 0u;
    if (tid == 0) { sI = 0; sP = 0; sCmd = 0; }
    __syncthreads();

    // bitonic sort ascending (rank r lives at index 255-r)
    for (int k = 2; k <= 256; k <<= 1) {
        for (int j = k >> 1; j > 0; j >>= 1) {
            int ixj = tid ^ j;
            if (ixj > tid) {
                u64 a = sC[tid], b = sC[ixj];
                bool sw = ((tid & k) == 0) ? (a > b) : (a < b);
                if (sw) { sC[tid] = b; sC[ixj] = a; }
            }
            __syncthreads();
        }
    }

    // sweep
    while (true) {
        if (wid == 0) {
            int i = sI, P = sP;
            int cmd = 0;
            while (true) {
                i = __shfl_sync(0xffffffffu, i, 0);
                P = __shfl_sync(0xffffffffu, P, 0);
                if (i >= 256 && P == 0) { cmd = 2; break; }
                if (P == 0) {
                    // chunked commit of up to 32 ranks
                    int r = i + lid;
                    bool valid = r < 256;
                    u64 C = valid ? sC[255 - r] : 0ull;
                    int row = 255 - (int)(C & 0xffffffffu);
                    int a   = valid ? sArg[row] : -1;
                    bool bad = false;
                    unsigned validmask = __ballot_sync(0xffffffffu, valid);
                    unsigned peers = __match_any_sync(0xffffffffu, a) & validmask;
                    if (valid) {
                        bool masked = (sMask[a >> 5] >> (a & 31)) & 1u;
                        bool first  = (peers & ((1u << lid) - 1u)) == 0;
                        bad = masked || !first;
                    }
                    unsigned badmask = __ballot_sync(0xffffffffu, valid && bad);
                    int c = badmask ? ((int)__ffs(badmask) - 1) : 32;
                    int ncommit = min(c, 256 - i);
                    if (lid < ncommit) {
                        atomicOr(&sMask[a >> 5], 1u << (a & 31));
                        g_sel[row] = a;
                    }
                    __syncwarp();
                    i += ncommit;
                    if (c < 32 && i < 256) {
                        // rank i is bad: pop next candidate or fallback-rescan
                        u64 Cc = sC[255 - i];
                        int brow = 255 - (int)(Cc & 0xffffffffu);
                        i += 1;
                        int act = 0;
                        if (lid == 0) {
                            int ptr = sPtr[brow];
                            if (ptr < 4 && P < 15) {
                                u64 cd = cand[brow][ptr];
                                sPtr[brow] = ptr + 1;
                                int ix = (int)(0xffffffffu - (unsigned)(cd & 0xffffffffu));
                                sArg[brow] = ix;
                                float nk = unMono((unsigned)(cd >> 32)) - sLz[brow];
                                pC[P] = ((u64)monoKey(nk) << 32) | (unsigned)(255 - brow);
                                P = P + 1;
                            } else {
                                sRrow = brow;
                                act = 1;
                            }
                        }
                        act = __shfl_sync(0xffffffffu, act, 0);
                        if (act) { cmd = 1; break; }
                    }
                } else {
                    // serial merge: sorted head vs best pending (lane 0)
                    int act = 0;
                    if (lid == 0) {
                        bool haveS = i < 256;
                        u64 Cs = haveS ? sC[255 - i] : 0ull;
                        int bj = 0; u64 Cb = pC[0];
                        for (int j = 1; j < P; ++j)
                            if (pC[j] > Cb) { Cb = pC[j]; bj = j; }
                        bool pickP = !haveS || (Cb > Cs);
                        u64 C = pickP ? Cb : Cs;
                        int row = 255 - (int)(C & 0xffffffffu);
                        int a = sArg[row];
                        bool masked = (sMask[a >> 5] >> (a & 31)) & 1u;
                        if (!masked) {
                            // commit
                            if (pickP) { pC[bj] = pC[P - 1]; P--; }
                            else i++;
                            sMask[a >> 5] |= 1u << (a & 31);
                            g_sel[row] = a;
                        } else {
                            // consume source entry, then pop or rescan
                            if (pickP) { pC[bj] = pC[P - 1]; P--; }
                            else i++;
                            int ptr = sPtr[row];
                            if (ptr < 4 && P < 15) {
                                u64 cd = cand[row][ptr];
                                sPtr[row] = ptr + 1;
                                int ix = (int)(0xffffffffu - (unsigned)(cd & 0xffffffffu));
                                sArg[row] = ix;
                                float nk = unMono((unsigned)(cd >> 32)) - sLz[row];
                                pC[P] = ((u64)monoKey(nk) << 32) | (unsigned)(255 - row);
                                P = P + 1;
                            } else {
                                sRrow = row;
                                act = 1;
                            }
                        }
                    }
                    act = __shfl_sync(0xffffffffu, act, 0);
                    if (act) { cmd = 1; break; }
                }
            }
            if (lid == 0) { sCmd = cmd; sI = i; sP = P; }
        }
        __syncthreads();
        if (sCmd == 2) break;

        // full-block fallback rescan of sRrow over unmasked columns
        {
            const int row = sRrow;
            const float* trow = g_t + (size_t)row * N_FEAT;
            float bv = negInf(); int bi = 0x7fffffff;
            for (int n = tid; n < N_FEAT; n += 256) {
                if (!((sMask[n >> 5] >> (n & 31)) & 1u)) {
                    float v = trow[n];
                    if (v > bv) { bv = v; bi = n; }
                }
            }
            warpReducePair(bv, bi);
            if (lid == 0) { redV[wid] = bv; redI[wid] = bi; }
            __syncthreads();
            if (tid < 32) {
                bv = (tid < 8) ? redV[tid] : negInf();
                bi = (tid < 8) ? redI[tid] : 0x7fffffff;
                warpReducePair(bv, bi);
                if (tid == 0) {
                    sArg[row] = bi;
                    sPtr[row] = 4;   // stays list-exhausted
                    float nk = bv - sLz[row];
                    pC[sP] = ((u64)monoKey(nk) << 32) | (unsigned)(255 - row);
                    sP = sP + 1;
                    sCmd = 0;
                }
            }
        }
        __syncthreads();
    }
}

// ---------------------------------------------------------------------------
// Kernel 4: Y[b,d] = X[b, sel[d]]  (dl has one 1 per row -> exact column gather)
// ---------------------------------------------------------------------------
__global__ void __launch_bounds__(256)
k_gather(const float* __restrict__ X, float* __restrict__ Y)
{
    const int tid = threadIdx.x;
    const int idx = blockIdx.x * 256 + tid;
    const int b = idx >> 8;
    const int y = g_sel[tid];             // tid == d
    Y[idx] = X[(size_t)b * N_FEAT + y];
}

extern "C" void kernel_launch(void* const* d_in, const int* in_sizes, int n_in,
                              void* d_out, int out_size)
{
    const float* X       = (const float*)d_in[0];
    const float* u       = (const float*)d_in[1];
    const float* tinyW   = (const float*)d_in[2];
    const float* uniform = (const float*)d_in[3];
    float* Y = (float*)d_out;

    const int smem = (TILE_N * BINS + DOUT * (TILE_N + 1) + TILE_N) * (int)sizeof(float);
    cudaFuncSetAttribute(k_compute_t, cudaFuncAttributeMaxDynamicSharedMemorySize, smem);

    k_compute_t<<<NBLK, 256, smem>>>(u, tinyW, uniform);
    k_top4<<<DOUT, 256>>>();
    k_select<<<1, 256>>>();
    k_gather<<<(BATCH * DOUT) / 256, 256>>>(X, Y);
}